// round 8
// baseline (speedup 1.0000x reference)
#include <cuda_runtime.h>
#include <cstdint>

#define BB   2
#define NN   4096
#define DD   256
#define PC   320     // 3*64 (Wk) + 128 (W_lin)
#define DOUT 64

// ---------------- scratch ---------------------------------------------------
__device__ float g_Kb[(size_t)BB * NN * NN];
__device__ float g_Kw[(size_t)BB * NN * NN];
__device__ float g_sq[BB * NN];
__device__ float g_Wcat[DD * PC];                 // tf32-rounded
__device__ float g_Xt[(size_t)BB * NN * DD];      // tf32-rounded x
__device__ float g_P[(size_t)BB * NN * PC];       // fp32 x@Wcat
__device__ float g_H2r[(size_t)BB * NN * DOUT];   // tf32-rounded h2
__device__ float g_t[(size_t)2 * BB * NN * DOUT]; // tf32-rounded stage-1 result
__device__ float g_t0[(size_t)2 * BB * NN * DOUT];
__device__ float g_t1[(size_t)2 * BB * NN * DOUT];
__device__ float g_g0[(size_t)2 * BB * NN * DOUT];
__device__ float g_g1[(size_t)2 * BB * NN * DOUT];

// ---------------- helpers ---------------------------------------------------
__device__ __forceinline__ uint32_t f2tf(float f) {
    uint32_t u;
    asm volatile("cvt.rna.tf32.f32 %0, %1;" : "=r"(u) : "f"(f));
    return u;
}

__device__ __forceinline__ void mma_tf32(float c[4], const uint32_t a[4], const uint32_t b[2]) {
    asm volatile(
        "mma.sync.aligned.m16n8k8.row.col.f32.tf32.tf32.f32 "
        "{%0,%1,%2,%3}, {%4,%5,%6,%7}, {%8,%9}, {%0,%1,%2,%3};\n"
        : "+f"(c[0]), "+f"(c[1]), "+f"(c[2]), "+f"(c[3])
        : "r"(a[0]), "r"(a[1]), "r"(a[2]), "r"(a[3]),
          "r"(b[0]), "r"(b[1]));
}

__device__ __forceinline__ void cpa16(uint32_t dst, const float* src) {
    asm volatile("cp.async.cg.shared.global [%0], [%1], 16;\n" :: "r"(dst), "l"(src));
}
#define CP_COMMIT() asm volatile("cp.async.commit_group;\n" ::: "memory")
#define CP_WAIT1()  asm volatile("cp.async.wait_group 1;\n" ::: "memory")
#define CP_WAIT2()  asm volatile("cp.async.wait_group 2;\n" ::: "memory")

// Cubic B-spline on uniform knots {0,.25,.5,.75,1}, closed form via symmetry.
// s = 4t in [0,4]; fold v = 2-|s-2| in [0,2]; v<1: v^3/6, else (-3v^3+12v^2-12v+4)/6.
__device__ __forceinline__ float b3fold(float v) {
    float outer = v * v * v * (1.f / 6.f);
    float inner = (((-3.f * v + 12.f) * v - 12.f) * v + 4.f) * (1.f / 6.f);
    return (v < 1.f) ? outer : inner;
}
__device__ __forceinline__ float bk_eval(float t) {
    float v = 2.f - fabsf(4.f * t - 2.f);
    return b3fold(v);                          // t=1 -> v=0 -> 0 (matches recursion)
}
// wavelet = B(2t) - B(2t-1); disjoint supports -> signed fold of (8t mod 4)
__device__ __forceinline__ float wk_eval(float t) {
    float sg = 8.f * t;
    bool lo = (sg < 4.f);
    float sp = lo ? sg : sg - 4.f;
    float v = 2.f - fabsf(sp - 2.f);
    float r = b3fold(v);
    return lo ? r : -r;
}

// ---------------- tiny prep kernels -----------------------------------------
__global__ void k_xcvt(const float* __restrict__ x) {
    int i = blockIdx.x * 256 + threadIdx.x;
    float4 v = ((const float4*)x)[i];
    uint4 o;
    o.x = f2tf(v.x); o.y = f2tf(v.y); o.z = f2tf(v.z); o.w = f2tf(v.w);
    ((uint4*)g_Xt)[i] = o;
}

__global__ void k_sqnorm(const float* __restrict__ x) {
    int row  = blockIdx.x * 8 + (threadIdx.x >> 5);
    int lane = threadIdx.x & 31;
    const float* xr = x + (size_t)row * DD;
    float s = 0.f;
    #pragma unroll
    for (int i = lane; i < DD; i += 32) { float v = xr[i]; s += v * v; }
    #pragma unroll
    for (int o = 16; o; o >>= 1) s += __shfl_xor_sync(0xffffffffu, s, o);
    if (lane == 0) g_sq[row] = s;
}

__global__ void k_wcat(const float* __restrict__ Wk, const float* __restrict__ Wl) {
    int i = blockIdx.x * 256 + threadIdx.x;
    if (i >= DD * PC) return;
    int d = i / PC, cidx = i % PC;
    float v;
    if (cidx < 192) v = Wk[(size_t)(cidx / 64) * DD * 64 + (size_t)d * 64 + (cidx & 63)];
    else            v = Wl[(size_t)d * 128 + (cidx - 192)];
    g_Wcat[i] = __uint_as_float(f2tf(v));
}

// ---------------- kernel: Gram + spline --------------------------------------
// Block tile 128(m) x 64(n); 8 warps 4m x 2n, warp tile 32x32.
// 3-stage cp.async ring, ONE barrier per chunk. Static smem 3*3840*4 = 46 KB.
__global__ __launch_bounds__(256) void k_gram() {
    __shared__ float sm[3 * 3840];          // per stage: A 128x20 + B 64x20
    int h   = blockIdx.x & 1;
    int idx = blockIdx.x >> 1;              // 0..527 triangular super-tile
    int b   = blockIdx.y;
    int tj = (int)((sqrtf(8.f * idx + 1.f) - 1.f) * 0.5f);
    while ((tj + 1) * (tj + 2) / 2 <= idx) ++tj;
    while (tj * (tj + 1) / 2 > idx) --tj;
    int ti = idx - tj * (tj + 1) / 2;

    int tid = threadIdx.x, lane = tid & 31, wid = tid >> 5;
    int wm = wid & 3, wn = wid >> 2;
    const float* Xa = g_Xt + ((size_t)b * NN + (size_t)ti * 128) * DD;
    const float* Xb = g_Xt + ((size_t)b * NN + (size_t)tj * 128 + (size_t)h * 64) * DD;
    uint32_t sb = (uint32_t)__cvta_generic_to_shared(sm);

    float c[2][4][4];
    #pragma unroll
    for (int i = 0; i < 2; i++)
        #pragma unroll
        for (int j = 0; j < 4; j++)
            #pragma unroll
            for (int r = 0; r < 4; r++) c[i][j][r] = 0.f;

    int arow_l = tid >> 2,         apart_l = (tid & 3) << 2;
    int arow_h = (256 + tid) >> 2, apart_h = ((256 + tid) & 3) << 2;
    int brow   = tid >> 2,         bpart   = (tid & 3) << 2;

    // prologue: chunks 0,1 -> stages 0,1
    #pragma unroll
    for (int pc = 0; pc < 2; ++pc) {
        uint32_t sA = sb + pc * 3840 * 4, sB = sA + 2560 * 4;
        int k0 = pc * 16;
        cpa16(sA + (arow_l * 20 + apart_l) * 4, Xa + (size_t)arow_l * DD + k0 + apart_l);
        cpa16(sA + (arow_h * 20 + apart_h) * 4, Xa + (size_t)arow_h * DD + k0 + apart_h);
        cpa16(sB + (brow * 20 + bpart) * 4, Xb + (size_t)brow * DD + k0 + bpart);
        CP_COMMIT();
    }

    for (int cc = 0; cc < 16; ++cc) {
        CP_WAIT1();
        __syncthreads();
        if (cc + 2 < 16) {
            int st = (cc + 2) % 3, k0 = (cc + 2) * 16;
            uint32_t sA = sb + (st * 3840) * 4, sB = sA + 2560 * 4;
            cpa16(sA + (arow_l * 20 + apart_l) * 4, Xa + (size_t)arow_l * DD + k0 + apart_l);
            cpa16(sA + (arow_h * 20 + apart_h) * 4, Xa + (size_t)arow_h * DD + k0 + apart_h);
            cpa16(sB + (brow * 20 + bpart) * 4, Xb + (size_t)brow * DD + k0 + bpart);
        }
        CP_COMMIT();
        const float* A  = sm + (cc % 3) * 3840;
        const float* Bp = A + 2560;
        #pragma unroll
        for (int ks = 0; ks < 2; ++ks) {
            int kk = ks * 8 + (lane & 3);
            uint32_t a[2][4], bf[4][2];
            #pragma unroll
            for (int mi = 0; mi < 2; mi++) {
                int mr = wm * 32 + mi * 16 + (lane >> 2);
                a[mi][0] = __float_as_uint(A[mr * 20 + kk]);
                a[mi][1] = __float_as_uint(A[(mr + 8) * 20 + kk]);
                a[mi][2] = __float_as_uint(A[mr * 20 + kk + 4]);
                a[mi][3] = __float_as_uint(A[(mr + 8) * 20 + kk + 4]);
            }
            #pragma unroll
            for (int ni = 0; ni < 4; ni++) {
                int nc = wn * 32 + ni * 8 + (lane >> 2);
                bf[ni][0] = __float_as_uint(Bp[nc * 20 + kk]);
                bf[ni][1] = __float_as_uint(Bp[nc * 20 + kk + 4]);
            }
            #pragma unroll
            for (int mi = 0; mi < 2; mi++)
                #pragma unroll
                for (int ni = 0; ni < 4; ni++)
                    mma_tf32(c[mi][ni], a[mi], bf[ni]);
        }
    }

    float* Kb = g_Kb + (size_t)b * NN * NN;
    float* Kw = g_Kw + (size_t)b * NN * NN;
    const float* sq = g_sq + b * NN;
    int i0 = ti * 128 + wm * 32, j0 = tj * 128 + h * 64 + wn * 32;
    bool mir = (ti != tj);
    #pragma unroll
    for (int mi = 0; mi < 2; mi++)
        #pragma unroll
        for (int ni = 0; ni < 4; ni++)
            #pragma unroll
            for (int r = 0; r < 4; r++) {
                int i = i0 + mi * 16 + (lane >> 2) + ((r >> 1) << 3);
                int j = j0 + ni * 8 + ((lane & 3) << 1) + (r & 1);
                float d2 = sq[i] + sq[j] - 2.f * c[mi][ni][r];
                d2 = fmaxf(d2, 0.f);
                float t = __expf(d2 * (-1.f / 512.f));
                float bk = __uint_as_float(f2tf(bk_eval(t)));
                float wk = __uint_as_float(f2tf(wk_eval(t)));
                Kb[(size_t)i * NN + j] = bk;
                Kw[(size_t)i * NN + j] = wk;
                if (mir) {
                    Kb[(size_t)j * NN + i] = bk;
                    Kw[(size_t)j * NN + i] = wk;
                }
            }
}

// ---------------- kernel: projection P = x @ Wcat (R2, unchanged) -----------
__global__ __launch_bounds__(256) void k_proj() {
    __shared__ float sm[2 * 3648];
    int c0 = blockIdx.x * 64, byr = blockIdx.y;
    int tid = threadIdx.x, lane = tid & 31, wid = tid >> 5;
    int wm = wid & 1, wn = wid >> 1;
    const float* Xa = g_Xt + (size_t)byr * 128 * DD;
    uint32_t sb = (uint32_t)__cvta_generic_to_shared(sm);

    float c[4][2][4];
    #pragma unroll
    for (int i = 0; i < 4; i++)
        #pragma unroll
        for (int j = 0; j < 2; j++)
            #pragma unroll
            for (int r = 0; r < 4; r++) c[i][j][r] = 0.f;

    {
        uint32_t sA = sb, sB = sb + 2560 * 4;
        #pragma unroll
        for (int it = 0; it < 2; ++it) {
            int id = it * 256 + tid;
            int row = id >> 2, part = (id & 3) << 2;
            cpa16(sA + (row * 20 + part) * 4, Xa + (size_t)row * DD + part);
        }
        int kk = tid >> 4, cq = (tid & 15) << 2;
        cpa16(sB + (kk * 68 + cq) * 4, g_Wcat + (size_t)kk * PC + c0 + cq);
    }
    CP_COMMIT();

    for (int cc = 0; cc < 16; ++cc) {
        if (cc + 1 < 16) {
            int s = (cc + 1) & 1, k0 = (cc + 1) * 16;
            uint32_t sA = sb + (s * 3648) * 4, sB = sA + 2560 * 4;
            #pragma unroll
            for (int it = 0; it < 2; ++it) {
                int id = it * 256 + tid;
                int row = id >> 2, part = (id & 3) << 2;
                cpa16(sA + (row * 20 + part) * 4, Xa + (size_t)row * DD + k0 + part);
            }
            int kk = tid >> 4, cq = (tid & 15) << 2;
            cpa16(sB + (kk * 68 + cq) * 4, g_Wcat + (size_t)(k0 + kk) * PC + c0 + cq);
        }
        CP_COMMIT();
        CP_WAIT1();
        __syncthreads();
        const float* A  = sm + (cc & 1) * 3648;
        const float* Bp = A + 2560;
        #pragma unroll
        for (int ks = 0; ks < 2; ++ks) {
            int kk = ks * 8 + (lane & 3);
            uint32_t a[4][4], bf[2][2];
            #pragma unroll
            for (int mi = 0; mi < 4; mi++) {
                int mr = wm * 64 + mi * 16 + (lane >> 2);
                a[mi][0] = __float_as_uint(A[mr * 20 + kk]);
                a[mi][1] = __float_as_uint(A[(mr + 8) * 20 + kk]);
                a[mi][2] = __float_as_uint(A[mr * 20 + kk + 4]);
                a[mi][3] = __float_as_uint(A[(mr + 8) * 20 + kk + 4]);
            }
            #pragma unroll
            for (int ni = 0; ni < 2; ni++) {
                int nc = wn * 16 + ni * 8 + (lane >> 2);
                bf[ni][0] = __float_as_uint(Bp[kk * 68 + nc]);
                bf[ni][1] = __float_as_uint(Bp[(kk + 4) * 68 + nc]);
            }
            #pragma unroll
            for (int mi = 0; mi < 4; mi++)
                #pragma unroll
                for (int ni = 0; ni < 2; ni++)
                    mma_tf32(c[mi][ni], a[mi], bf[ni]);
        }
        __syncthreads();
    }

    #pragma unroll
    for (int mi = 0; mi < 4; mi++)
        #pragma unroll
        for (int ni = 0; ni < 2; ni++)
            #pragma unroll
            for (int r = 0; r < 4; r++) {
                int row = byr * 128 + wm * 64 + mi * 16 + (lane >> 2) + ((r >> 1) << 3);
                int col = c0 + wn * 16 + ni * 8 + ((lane & 3) << 1) + (r & 1);
                float v = c[mi][ni][r];
                g_P[(size_t)row * PC + col] = v;
                if (col >= 128 && col < 192)
                    g_H2r[(size_t)row * DOUT + (col - 128)] = __uint_as_float(f2tf(v));
            }
}

// ---------------- kernel: SpMM partial, split-K x2, 4-stage pipeline ---------
// 64x64 tile, KC=32. Dynamic smem 4 * 4480 * 4 = 71680 B; 3 chunks in flight.
__global__ __launch_bounds__(256) void k_spmm(int stage) {
    extern __shared__ float smd[];
    int rt = blockIdx.x, b = blockIdx.y;
    int type = blockIdx.z >> 1, sp = blockIdx.z & 1;
    int mbase = sp * (NN / 2);
    const float* Km = (type ? g_Kw : g_Kb) + (size_t)b * NN * NN;
    const float* H;
    float* Out;
    if (stage == 1) {
        H   = g_H2r + (size_t)b * NN * DOUT;
        Out = (sp ? g_t1 : g_t0) + ((size_t)type * BB + b) * NN * DOUT;
    } else {
        H   = g_t + ((size_t)type * BB + b) * NN * DOUT;
        Out = (sp ? g_g1 : g_g0) + ((size_t)type * BB + b) * NN * DOUT;
    }
    int tid = threadIdx.x, lane = tid & 31, wid = tid >> 5;
    int wm = wid & 3, wn = wid >> 2;
    uint32_t sb = (uint32_t)__cvta_generic_to_shared(smd);

    float c[4][4];
    #pragma unroll
    for (int i = 0; i < 4; i++)
        #pragma unroll
        for (int r = 0; r < 4; r++) c[i][r] = 0.f;

    const int NCH = 64;   // 2048 / 32
    // prologue: chunks 0..2 -> stages 0..2
    #pragma unroll
    for (int pc = 0; pc < 3; ++pc) {
        uint32_t sA = sb + pc * 4480 * 4, sB = sA + 2304 * 4;
        int m0 = mbase + pc * 32;
        #pragma unroll
        for (int it = 0; it < 2; ++it) {
            int id = it * 256 + tid;
            int row = id >> 3, part = (id & 7) << 2;
            cpa16(sA + (row * 36 + part) * 4, Km + (size_t)(rt * 64 + row) * NN + m0 + part);
            int kk = id >> 4, cq = (id & 15) << 2;
            cpa16(sB + (kk * 68 + cq) * 4, H + (size_t)(m0 + kk) * DOUT + cq);
        }
        CP_COMMIT();
    }

    #pragma unroll 1
    for (int cc = 0; cc < NCH; ++cc) {
        CP_WAIT2();
        __syncthreads();
        if (cc + 3 < NCH) {
            int st = (cc + 3) & 3, m0 = mbase + (cc + 3) * 32;
            uint32_t sA = sb + (st * 4480) * 4, sB = sA + 2304 * 4;
            #pragma unroll
            for (int it = 0; it < 2; ++it) {
                int id = it * 256 + tid;
                int row = id >> 3, part = (id & 7) << 2;
                cpa16(sA + (row * 36 + part) * 4, Km + (size_t)(rt * 64 + row) * NN + m0 + part);
                int kk = id >> 4, cq = (id & 15) << 2;
                cpa16(sB + (kk * 68 + cq) * 4, H + (size_t)(m0 + kk) * DOUT + cq);
            }
        }
        CP_COMMIT();
        const float* A  = smd + (cc & 3) * 4480;
        const float* Bp = A + 2304;
        #pragma unroll
        for (int ks = 0; ks < 4; ++ks) {
            int kk = ks * 8 + (lane & 3);
            uint32_t a[4];
            int mr = wm * 16 + (lane >> 2);
            a[0] = __float_as_uint(A[mr * 36 + kk]);
            a[1] = __float_as_uint(A[(mr + 8) * 36 + kk]);
            a[2] = __float_as_uint(A[mr * 36 + kk + 4]);
            a[3] = __float_as_uint(A[(mr + 8) * 36 + kk + 4]);
            #pragma unroll
            for (int ni = 0; ni < 4; ni++) {
                int nc = wn * 32 + ni * 8 + (lane >> 2);
                uint32_t bf[2];
                bf[0] = __float_as_uint(Bp[kk * 68 + nc]);
                bf[1] = __float_as_uint(Bp[(kk + 4) * 68 + nc]);
                mma_tf32(c[ni], a, bf);
            }
        }
    }

    #pragma unroll
    for (int ni = 0; ni < 4; ni++)
        #pragma unroll
        for (int r = 0; r < 4; r++) {
            int row = rt * 64 + wm * 16 + (lane >> 2) + ((r >> 1) << 3);
            int col = wn * 32 + ni * 8 + ((lane & 3) << 1) + (r & 1);
            Out[(size_t)row * DOUT + col] = c[ni][r];
        }
}

// ---------------- combine stage-1 partials + Add, round to tf32 --------------
__global__ void k_comb1() {
    int i = blockIdx.x * 256 + threadIdx.x;            // over 2*BB*NN*DOUT
    int col = i & 63;
    int row = (i >> 6) & (NN - 1);
    int b   = (i >> 18) & (BB - 1);
    float v = g_t0[i] + g_t1[i] + g_P[((size_t)b * NN + row) * PC + 64 + col];
    g_t[i] = __uint_as_float(f2tf(v));
}

// ---------------- final epilogue ---------------------------------------------
__global__ void k_final(const float* __restrict__ b_lin, float* __restrict__ out) {
    int idx = blockIdx.x * 256 + threadIdx.x;          // over B*N*128
    int cidx = idx & 127;
    int n = (idx >> 7) & (NN - 1);
    int b = idx >> 19;
    int half = cidx >> 6, cc = cidx & 63;
    const float* P = g_P + ((size_t)b * NN + n) * PC;
    size_t gi = (((size_t)half * BB + b) * NN + n) * DOUT + cc;
    float g = g_g0[gi] + g_g1[gi];
    float v = P[cc] + g + P[192 + cidx] + b_lin[cidx];
    out[idx] = fmaxf(v, 0.f);
}

// ---------------- launch -----------------------------------------------------
extern "C" void kernel_launch(void* const* d_in, const int* in_sizes, int n_in,
                              void* d_out, int out_size) {
    const float* x  = (const float*)d_in[0];
    const float* Wk = (const float*)d_in[1];
    const float* Wl = (const float*)d_in[2];
    const float* bl = (const float*)d_in[3];
    float* out = (float*)d_out;

    static bool attr_done = false;
    if (!attr_done) {
        cudaFuncSetAttribute(k_spmm, cudaFuncAttributeMaxDynamicSharedMemorySize, 71680);
        attr_done = true;
    }

    k_xcvt<<<(BB * NN * DD / 4) / 256, 256>>>(x);
    k_sqnorm<<<BB * NN / 8, 256>>>(x);
    k_wcat<<<(DD * PC + 255) / 256, 256>>>(Wk, Wl);
    k_gram<<<dim3(1056, BB), 256>>>();
    k_proj<<<dim3(PC / 64, (BB * NN) / 128), 256>>>();
    k_spmm<<<dim3(NN / 64, BB, 4), 256, 71680>>>(1);
    k_comb1<<<(2 * BB * NN * DOUT) / 256, 256>>>();
    k_spmm<<<dim3(NN / 64, BB, 4), 256, 71680>>>(2);
    k_final<<<(BB * NN * 128) / 256, 256>>>(bl, out);
}

// round 9
// speedup vs baseline: 1.5915x; 1.5915x over previous
#include <cuda_runtime.h>
#include <cstdint>

#define BB   2
#define NN   4096
#define DD   256
#define PC   320     // 3*64 (Wk) + 128 (W_lin)
#define DOUT 64

// ---------------- scratch ---------------------------------------------------
__device__ float g_Kb[(size_t)BB * NN * NN];
__device__ float g_Kw[(size_t)BB * NN * NN];
__device__ float g_sq[BB * NN];
__device__ float g_Wcat[DD * PC];                 // tf32-rounded
__device__ float g_Xt[(size_t)BB * NN * DD];      // tf32-rounded x
__device__ float g_P[(size_t)BB * NN * PC];       // fp32 x@Wcat
__device__ float g_H2r[(size_t)BB * NN * DOUT];   // tf32-rounded h2
__device__ float g_t[(size_t)2 * BB * NN * DOUT]; // tf32-rounded stage-1 result
__device__ float g_t0[(size_t)2 * BB * NN * DOUT];
__device__ float g_t1[(size_t)2 * BB * NN * DOUT];
__device__ float g_t2[(size_t)2 * BB * NN * DOUT];
__device__ float g_t3[(size_t)2 * BB * NN * DOUT];
__device__ float g_g0[(size_t)2 * BB * NN * DOUT];
__device__ float g_g1[(size_t)2 * BB * NN * DOUT];
__device__ float g_g2[(size_t)2 * BB * NN * DOUT];
__device__ float g_g3[(size_t)2 * BB * NN * DOUT];

// ---------------- helpers ---------------------------------------------------
__device__ __forceinline__ uint32_t f2tf(float f) {
    uint32_t u;
    asm volatile("cvt.rna.tf32.f32 %0, %1;" : "=r"(u) : "f"(f));
    return u;
}

__device__ __forceinline__ void mma_tf32(float c[4], const uint32_t a[4], const uint32_t b[2]) {
    asm volatile(
        "mma.sync.aligned.m16n8k8.row.col.f32.tf32.tf32.f32 "
        "{%0,%1,%2,%3}, {%4,%5,%6,%7}, {%8,%9}, {%0,%1,%2,%3};\n"
        : "+f"(c[0]), "+f"(c[1]), "+f"(c[2]), "+f"(c[3])
        : "r"(a[0]), "r"(a[1]), "r"(a[2]), "r"(a[3]),
          "r"(b[0]), "r"(b[1]));
}

__device__ __forceinline__ void cpa16(uint32_t dst, const float* src) {
    asm volatile("cp.async.cg.shared.global [%0], [%1], 16;\n" :: "r"(dst), "l"(src));
}
#define CP_COMMIT() asm volatile("cp.async.commit_group;\n" ::: "memory")
#define CP_WAIT1()  asm volatile("cp.async.wait_group 1;\n" ::: "memory")

// Closed-form cubic B-spline on uniform knots {0,.25,.5,.75,1} (== reference
// Cox-de Boor recursion; empirically verified R8, rel_err unchanged).
__device__ __forceinline__ float b3fold(float v) {
    float outer = v * v * v * (1.f / 6.f);
    float inner = (((-3.f * v + 12.f) * v - 12.f) * v + 4.f) * (1.f / 6.f);
    return (v < 1.f) ? outer : inner;
}
__device__ __forceinline__ float bk_eval(float t) {
    float v = 2.f - fabsf(4.f * t - 2.f);
    return b3fold(v);
}
__device__ __forceinline__ float wk_eval(float t) {
    float sg = 8.f * t;
    bool lo = (sg < 4.f);
    float sp = lo ? sg : sg - 4.f;
    float v = 2.f - fabsf(sp - 2.f);
    float r = b3fold(v);
    return lo ? r : -r;
}

// ---------------- tiny prep kernels -----------------------------------------
__global__ void k_xcvt(const float* __restrict__ x) {
    int i = blockIdx.x * 256 + threadIdx.x;
    float4 v = ((const float4*)x)[i];
    uint4 o;
    o.x = f2tf(v.x); o.y = f2tf(v.y); o.z = f2tf(v.z); o.w = f2tf(v.w);
    ((uint4*)g_Xt)[i] = o;
}

__global__ void k_sqnorm(const float* __restrict__ x) {
    int row  = blockIdx.x * 8 + (threadIdx.x >> 5);
    int lane = threadIdx.x & 31;
    const float* xr = x + (size_t)row * DD;
    float s = 0.f;
    #pragma unroll
    for (int i = lane; i < DD; i += 32) { float v = xr[i]; s += v * v; }
    #pragma unroll
    for (int o = 16; o; o >>= 1) s += __shfl_xor_sync(0xffffffffu, s, o);
    if (lane == 0) g_sq[row] = s;
}

__global__ void k_wcat(const float* __restrict__ Wk, const float* __restrict__ Wl) {
    int i = blockIdx.x * 256 + threadIdx.x;
    if (i >= DD * PC) return;
    int d = i / PC, cidx = i % PC;
    float v;
    if (cidx < 192) v = Wk[(size_t)(cidx / 64) * DD * 64 + (size_t)d * 64 + (cidx & 63)];
    else            v = Wl[(size_t)d * 128 + (cidx - 192)];
    g_Wcat[i] = __uint_as_float(f2tf(v));
}

// ---------------- kernel: Gram + spline (R7 structure, closed-form spline) ---
// Block tile 128(m) x 64(n); 8 warps 4m x 2n, warp tile 32x32.
// 2-stage cp.async pipeline. Static smem: 2*3840*4 = 30 KB. 4 blocks/SM pinned.
__global__ __launch_bounds__(256, 4) void k_gram() {
    __shared__ float sm[2 * 3840];          // per stage: A 128x20 + B 64x20
    int h   = blockIdx.x & 1;
    int idx = blockIdx.x >> 1;              // 0..527 triangular super-tile
    int b   = blockIdx.y;
    int tj = (int)((sqrtf(8.f * idx + 1.f) - 1.f) * 0.5f);
    while ((tj + 1) * (tj + 2) / 2 <= idx) ++tj;
    while (tj * (tj + 1) / 2 > idx) --tj;
    int ti = idx - tj * (tj + 1) / 2;

    int tid = threadIdx.x, lane = tid & 31, wid = tid >> 5;
    int wm = wid & 3, wn = wid >> 2;
    const float* Xa = g_Xt + ((size_t)b * NN + (size_t)ti * 128) * DD;
    const float* Xb = g_Xt + ((size_t)b * NN + (size_t)tj * 128 + (size_t)h * 64) * DD;
    uint32_t sb = (uint32_t)__cvta_generic_to_shared(sm);

    float c[2][4][4];
    #pragma unroll
    for (int i = 0; i < 2; i++)
        #pragma unroll
        for (int j = 0; j < 4; j++)
            #pragma unroll
            for (int r = 0; r < 4; r++) c[i][j][r] = 0.f;

    int arow_l = tid >> 2,         apart_l = (tid & 3) << 2;
    int arow_h = (256 + tid) >> 2, apart_h = ((256 + tid) & 3) << 2;
    int brow   = tid >> 2,         bpart   = (tid & 3) << 2;

    {   // prologue: chunk 0 -> stage 0
        uint32_t sA = sb, sB = sb + 2560 * 4;
        cpa16(sA + (arow_l * 20 + apart_l) * 4, Xa + (size_t)arow_l * DD + apart_l);
        cpa16(sA + (arow_h * 20 + apart_h) * 4, Xa + (size_t)arow_h * DD + apart_h);
        cpa16(sB + (brow * 20 + bpart) * 4, Xb + (size_t)brow * DD + bpart);
    }
    CP_COMMIT();

    for (int cc = 0; cc < 16; ++cc) {
        if (cc + 1 < 16) {
            int s = (cc + 1) & 1, k0 = (cc + 1) * 16;
            uint32_t sA = sb + (s * 3840) * 4, sB = sA + 2560 * 4;
            cpa16(sA + (arow_l * 20 + apart_l) * 4, Xa + (size_t)arow_l * DD + k0 + apart_l);
            cpa16(sA + (arow_h * 20 + apart_h) * 4, Xa + (size_t)arow_h * DD + k0 + apart_h);
            cpa16(sB + (brow * 20 + bpart) * 4, Xb + (size_t)brow * DD + k0 + bpart);
        }
        CP_COMMIT();
        CP_WAIT1();
        __syncthreads();
        const float* A  = sm + (cc & 1) * 3840;
        const float* Bp = A + 2560;
        #pragma unroll
        for (int ks = 0; ks < 2; ++ks) {
            int kk = ks * 8 + (lane & 3);
            uint32_t a[2][4], bf[4][2];
            #pragma unroll
            for (int mi = 0; mi < 2; mi++) {
                int mr = wm * 32 + mi * 16 + (lane >> 2);
                a[mi][0] = __float_as_uint(A[mr * 20 + kk]);
                a[mi][1] = __float_as_uint(A[(mr + 8) * 20 + kk]);
                a[mi][2] = __float_as_uint(A[mr * 20 + kk + 4]);
                a[mi][3] = __float_as_uint(A[(mr + 8) * 20 + kk + 4]);
            }
            #pragma unroll
            for (int ni = 0; ni < 4; ni++) {
                int nc = wn * 32 + ni * 8 + (lane >> 2);
                bf[ni][0] = __float_as_uint(Bp[nc * 20 + kk]);
                bf[ni][1] = __float_as_uint(Bp[nc * 20 + kk + 4]);
            }
            #pragma unroll
            for (int mi = 0; mi < 2; mi++)
                #pragma unroll
                for (int ni = 0; ni < 4; ni++)
                    mma_tf32(c[mi][ni], a[mi], bf[ni]);
        }
        __syncthreads();
    }

    float* Kb = g_Kb + (size_t)b * NN * NN;
    float* Kw = g_Kw + (size_t)b * NN * NN;
    const float* sq = g_sq + b * NN;
    int i0 = ti * 128 + wm * 32, j0 = tj * 128 + h * 64 + wn * 32;
    bool mir = (ti != tj);
    #pragma unroll
    for (int mi = 0; mi < 2; mi++)
        #pragma unroll
        for (int ni = 0; ni < 4; ni++)
            #pragma unroll
            for (int r = 0; r < 4; r++) {
                int i = i0 + mi * 16 + (lane >> 2) + ((r >> 1) << 3);
                int j = j0 + ni * 8 + ((lane & 3) << 1) + (r & 1);
                float d2 = sq[i] + sq[j] - 2.f * c[mi][ni][r];
                d2 = fmaxf(d2, 0.f);
                float t = __expf(d2 * (-1.f / 512.f));
                float bk = __uint_as_float(f2tf(bk_eval(t)));
                float wk = __uint_as_float(f2tf(wk_eval(t)));
                Kb[(size_t)i * NN + j] = bk;
                Kw[(size_t)i * NN + j] = wk;
                if (mir) {
                    Kb[(size_t)j * NN + i] = bk;
                    Kw[(size_t)j * NN + i] = wk;
                }
            }
}

// ---------------- kernel: projection P = x @ Wcat (R2, unchanged) -----------
__global__ __launch_bounds__(256) void k_proj() {
    __shared__ float sm[2 * 3648];
    int c0 = blockIdx.x * 64, byr = blockIdx.y;
    int tid = threadIdx.x, lane = tid & 31, wid = tid >> 5;
    int wm = wid & 1, wn = wid >> 1;
    const float* Xa = g_Xt + (size_t)byr * 128 * DD;
    uint32_t sb = (uint32_t)__cvta_generic_to_shared(sm);

    float c[4][2][4];
    #pragma unroll
    for (int i = 0; i < 4; i++)
        #pragma unroll
        for (int j = 0; j < 2; j++)
            #pragma unroll
            for (int r = 0; r < 4; r++) c[i][j][r] = 0.f;

    {
        uint32_t sA = sb, sB = sb + 2560 * 4;
        #pragma unroll
        for (int it = 0; it < 2; ++it) {
            int id = it * 256 + tid;
            int row = id >> 2, part = (id & 3) << 2;
            cpa16(sA + (row * 20 + part) * 4, Xa + (size_t)row * DD + part);
        }
        int kk = tid >> 4, cq = (tid & 15) << 2;
        cpa16(sB + (kk * 68 + cq) * 4, g_Wcat + (size_t)kk * PC + c0 + cq);
    }
    CP_COMMIT();

    for (int cc = 0; cc < 16; ++cc) {
        if (cc + 1 < 16) {
            int s = (cc + 1) & 1, k0 = (cc + 1) * 16;
            uint32_t sA = sb + (s * 3648) * 4, sB = sA + 2560 * 4;
            #pragma unroll
            for (int it = 0; it < 2; ++it) {
                int id = it * 256 + tid;
                int row = id >> 2, part = (id & 3) << 2;
                cpa16(sA + (row * 20 + part) * 4, Xa + (size_t)row * DD + k0 + part);
            }
            int kk = tid >> 4, cq = (tid & 15) << 2;
            cpa16(sB + (kk * 68 + cq) * 4, g_Wcat + (size_t)(k0 + kk) * PC + c0 + cq);
        }
        CP_COMMIT();
        CP_WAIT1();
        __syncthreads();
        const float* A  = sm + (cc & 1) * 3648;
        const float* Bp = A + 2560;
        #pragma unroll
        for (int ks = 0; ks < 2; ++ks) {
            int kk = ks * 8 + (lane & 3);
            uint32_t a[4][4], bf[2][2];
            #pragma unroll
            for (int mi = 0; mi < 4; mi++) {
                int mr = wm * 64 + mi * 16 + (lane >> 2);
                a[mi][0] = __float_as_uint(A[mr * 20 + kk]);
                a[mi][1] = __float_as_uint(A[(mr + 8) * 20 + kk]);
                a[mi][2] = __float_as_uint(A[mr * 20 + kk + 4]);
                a[mi][3] = __float_as_uint(A[(mr + 8) * 20 + kk + 4]);
            }
            #pragma unroll
            for (int ni = 0; ni < 2; ni++) {
                int nc = wn * 16 + ni * 8 + (lane >> 2);
                bf[ni][0] = __float_as_uint(Bp[kk * 68 + nc]);
                bf[ni][1] = __float_as_uint(Bp[(kk + 4) * 68 + nc]);
            }
            #pragma unroll
            for (int mi = 0; mi < 4; mi++)
                #pragma unroll
                for (int ni = 0; ni < 2; ni++)
                    mma_tf32(c[mi][ni], a[mi], bf[ni]);
        }
        __syncthreads();
    }

    #pragma unroll
    for (int mi = 0; mi < 4; mi++)
        #pragma unroll
        for (int ni = 0; ni < 2; ni++)
            #pragma unroll
            for (int r = 0; r < 4; r++) {
                int row = byr * 128 + wm * 64 + mi * 16 + (lane >> 2) + ((r >> 1) << 3);
                int col = c0 + wn * 16 + ni * 8 + ((lane & 3) << 1) + (r & 1);
                float v = c[mi][ni][r];
                g_P[(size_t)row * PC + col] = v;
                if (col >= 128 && col < 192)
                    g_H2r[(size_t)row * DOUT + (col - 128)] = __uint_as_float(f2tf(v));
            }
}

// ---------------- kernel: SpMM partial, split-K x4 (R7 loop shape) -----------
// 64x64 tile, KC=32, 2-stage pipeline, static smem 2*4480*4 = 35.8 KB.
__global__ __launch_bounds__(256, 4) void k_spmm(int stage) {
    __shared__ float sm[2 * 4480];
    int rt = blockIdx.x, b = blockIdx.y;
    int type = blockIdx.z >> 2, sp = blockIdx.z & 3;
    int mbase = sp * (NN / 4);
    const float* Km = (type ? g_Kw : g_Kb) + (size_t)b * NN * NN;
    const float* H;
    float* Out;
    if (stage == 1) {
        H   = g_H2r + (size_t)b * NN * DOUT;
        float* outs[4] = {g_t0, g_t1, g_t2, g_t3};
        Out = outs[sp] + ((size_t)type * BB + b) * NN * DOUT;
    } else {
        H   = g_t + ((size_t)type * BB + b) * NN * DOUT;
        float* outs[4] = {g_g0, g_g1, g_g2, g_g3};
        Out = outs[sp] + ((size_t)type * BB + b) * NN * DOUT;
    }
    int tid = threadIdx.x, lane = tid & 31, wid = tid >> 5;
    int wm = wid & 3, wn = wid >> 2;
    uint32_t sb = (uint32_t)__cvta_generic_to_shared(sm);

    float c[4][4];
    #pragma unroll
    for (int i = 0; i < 4; i++)
        #pragma unroll
        for (int r = 0; r < 4; r++) c[i][r] = 0.f;

    const int NCH = 32;   // 1024 / 32
    {
        uint32_t sA = sb, sB = sb + 2304 * 4;
        #pragma unroll
        for (int it = 0; it < 2; ++it) {
            int id = it * 256 + tid;
            int row = id >> 3, part = (id & 7) << 2;
            cpa16(sA + (row * 36 + part) * 4, Km + (size_t)(rt * 64 + row) * NN + mbase + part);
            int kk = id >> 4, cq = (id & 15) << 2;
            cpa16(sB + (kk * 68 + cq) * 4, H + (size_t)(mbase + kk) * DOUT + cq);
        }
    }
    CP_COMMIT();

    #pragma unroll 1
    for (int cc = 0; cc < NCH; ++cc) {
        if (cc + 1 < NCH) {
            int s = (cc + 1) & 1, m0 = mbase + (cc + 1) * 32;
            uint32_t sA = sb + (s * 4480) * 4, sB = sA + 2304 * 4;
            #pragma unroll
            for (int it = 0; it < 2; ++it) {
                int id = it * 256 + tid;
                int row = id >> 3, part = (id & 7) << 2;
                cpa16(sA + (row * 36 + part) * 4, Km + (size_t)(rt * 64 + row) * NN + m0 + part);
                int kk = id >> 4, cq = (id & 15) << 2;
                cpa16(sB + (kk * 68 + cq) * 4, H + (size_t)(m0 + kk) * DOUT + cq);
            }
        }
        CP_COMMIT();
        CP_WAIT1();
        __syncthreads();
        const float* A  = sm + (cc & 1) * 4480;
        const float* Bp = A + 2304;
        #pragma unroll
        for (int ks = 0; ks < 4; ++ks) {
            int kk = ks * 8 + (lane & 3);
            uint32_t a[4];
            int mr = wm * 16 + (lane >> 2);
            a[0] = __float_as_uint(A[mr * 36 + kk]);
            a[1] = __float_as_uint(A[(mr + 8) * 36 + kk]);
            a[2] = __float_as_uint(A[mr * 36 + kk + 4]);
            a[3] = __float_as_uint(A[(mr + 8) * 36 + kk + 4]);
            #pragma unroll
            for (int ni = 0; ni < 4; ni++) {
                int nc = wn * 32 + ni * 8 + (lane >> 2);
                uint32_t bf[2];
                bf[0] = __float_as_uint(Bp[kk * 68 + nc]);
                bf[1] = __float_as_uint(Bp[(kk + 4) * 68 + nc]);
                mma_tf32(c[ni], a, bf);
            }
        }
        __syncthreads();
    }

    #pragma unroll
    for (int ni = 0; ni < 4; ni++)
        #pragma unroll
        for (int r = 0; r < 4; r++) {
            int row = rt * 64 + wm * 16 + (lane >> 2) + ((r >> 1) << 3);
            int col = wn * 32 + ni * 8 + ((lane & 3) << 1) + (r & 1);
            Out[(size_t)row * DOUT + col] = c[ni][r];
        }
}

// ---------------- combine stage-1 partials + Add, round to tf32 --------------
__global__ void k_comb1() {
    int i = blockIdx.x * 256 + threadIdx.x;            // over 2*BB*NN*DOUT
    int col = i & 63;
    int row = (i >> 6) & (NN - 1);
    int b   = (i >> 18) & (BB - 1);
    float v = (g_t0[i] + g_t1[i]) + (g_t2[i] + g_t3[i])
            + g_P[((size_t)b * NN + row) * PC + 64 + col];
    g_t[i] = __uint_as_float(f2tf(v));
}

// ---------------- final epilogue ---------------------------------------------
__global__ void k_final(const float* __restrict__ b_lin, float* __restrict__ out) {
    int idx = blockIdx.x * 256 + threadIdx.x;          // over B*N*128
    int cidx = idx & 127;
    int n = (idx >> 7) & (NN - 1);
    int b = idx >> 19;
    int half = cidx >> 6, cc = cidx & 63;
    const float* P = g_P + ((size_t)b * NN + n) * PC;
    size_t gi = (((size_t)half * BB + b) * NN + n) * DOUT + cc;
    float g = (g_g0[gi] + g_g1[gi]) + (g_g2[gi] + g_g3[gi]);
    float v = P[cc] + g + P[192 + cidx] + b_lin[cidx];
    out[idx] = fmaxf(v, 0.f);
}

// ---------------- launch -----------------------------------------------------
extern "C" void kernel_launch(void* const* d_in, const int* in_sizes, int n_in,
                              void* d_out, int out_size) {
    const float* x  = (const float*)d_in[0];
    const float* Wk = (const float*)d_in[1];
    const float* Wl = (const float*)d_in[2];
    const float* bl = (const float*)d_in[3];
    float* out = (float*)d_out;

    k_xcvt<<<(BB * NN * DD / 4) / 256, 256>>>(x);
    k_sqnorm<<<BB * NN / 8, 256>>>(x);
    k_wcat<<<(DD * PC + 255) / 256, 256>>>(Wk, Wl);
    k_gram<<<dim3(1056, BB), 256>>>();
    k_proj<<<dim3(PC / 64, (BB * NN) / 128), 256>>>();
    k_spmm<<<dim3(NN / 64, BB, 8), 256>>>(1);
    k_comb1<<<(2 * BB * NN * DOUT) / 256, 256>>>();
    k_spmm<<<dim3(NN / 64, BB, 8), 256>>>(2);
    k_final<<<(BB * NN * 128) / 256, 256>>>(bl, out);
}